// round 2
// baseline (speedup 1.0000x reference)
#include <cuda_runtime.h>
#include <cuda_bf16.h>

#define NN     40000
#define EE     640000
#define HH     128
#define GG     256
#define OUTD   10

// ---------------- scratch (no allocations allowed) ----------------
__device__ float g_bufA[(size_t)NN * HH];   // xw / layer outputs
__device__ float g_bufB[(size_t)NN * HH];
__device__ float g_dinv[NN];
__device__ float g_sums[GG * HH];
__device__ float g_cnt[GG];

// ---------------- degree / norm ----------------
__global__ void deg_init_k(float* deg) {
    int i = blockIdx.x * blockDim.x + threadIdx.x;
    if (i < NN) deg[i] = 1.0f;                 // self-loop
}

__global__ void deg_edges_k(const int* __restrict__ col, float* deg) {
    int e = blockIdx.x * blockDim.x + threadIdx.x;
    if (e < EE) atomicAdd(&deg[col[e]], 1.0f);
}

__global__ void dinv_k(float* dinv) {
    int i = blockIdx.x * blockDim.x + threadIdx.x;
    if (i < NN) dinv[i] = rsqrtf(dinv[i]);     // in-place: deg -> rsqrt(deg), deg>=1
}

// ---------------- GEMM: C[M,128] = (relu?)A[M,128] @ W[128,128] ----------------
// 64x128 tile, 256 threads, k-chunks of 16.
__global__ void gemm_k(const float* __restrict__ A, const float* __restrict__ W,
                       float* __restrict__ C, int applyRelu) {
    __shared__ float As[64][17];     // padded to kill bank conflicts
    __shared__ float Ws[16][128];

    int tid = threadIdx.x;
    int tx = tid & 15;               // 16 col-groups of 8
    int ty = tid >> 4;               // 16 row-groups of 4
    int rowBase = blockIdx.x * 64;

    float acc[4][8];
    #pragma unroll
    for (int i = 0; i < 4; i++)
        #pragma unroll
        for (int j = 0; j < 8; j++) acc[i][j] = 0.0f;

    for (int k0 = 0; k0 < 128; k0 += 16) {
        // load A tile: 64x16 floats, one float4 per thread
        {
            int idx = tid * 4;
            int r = idx >> 4;
            int c = idx & 15;
            float4 v = *reinterpret_cast<const float4*>(
                &A[(size_t)(rowBase + r) * HH + k0 + c]);
            if (applyRelu) {
                v.x = fmaxf(v.x, 0.0f); v.y = fmaxf(v.y, 0.0f);
                v.z = fmaxf(v.z, 0.0f); v.w = fmaxf(v.w, 0.0f);
            }
            As[r][c]     = v.x; As[r][c + 1] = v.y;
            As[r][c + 2] = v.z; As[r][c + 3] = v.w;
        }
        // load W tile: 16x128 floats, two float4 per thread
        {
            int idx = tid * 8;
            int r = idx >> 7;
            int c = idx & 127;
            float4 v0 = *reinterpret_cast<const float4*>(&W[(size_t)(k0 + r) * HH + c]);
            float4 v1 = *reinterpret_cast<const float4*>(&W[(size_t)(k0 + r) * HH + c + 4]);
            *reinterpret_cast<float4*>(&Ws[r][c])     = v0;
            *reinterpret_cast<float4*>(&Ws[r][c + 4]) = v1;
        }
        __syncthreads();

        #pragma unroll
        for (int kk = 0; kk < 16; kk++) {
            float a[4], b[8];
            #pragma unroll
            for (int i = 0; i < 4; i++) a[i] = As[ty * 4 + i][kk];
            float4 b0 = *reinterpret_cast<const float4*>(&Ws[kk][tx * 8]);
            float4 b1 = *reinterpret_cast<const float4*>(&Ws[kk][tx * 8 + 4]);
            b[0] = b0.x; b[1] = b0.y; b[2] = b0.z; b[3] = b0.w;
            b[4] = b1.x; b[5] = b1.y; b[6] = b1.z; b[7] = b1.w;
            #pragma unroll
            for (int i = 0; i < 4; i++)
                #pragma unroll
                for (int j = 0; j < 8; j++)
                    acc[i][j] = fmaf(a[i], b[j], acc[i][j]);
        }
        __syncthreads();
    }

    #pragma unroll
    for (int i = 0; i < 4; i++) {
        int row = rowBase + ty * 4 + i;
        #pragma unroll
        for (int j = 0; j < 8; j += 4) {
            float4 v = make_float4(acc[i][j], acc[i][j + 1], acc[i][j + 2], acc[i][j + 3]);
            *reinterpret_cast<float4*>(&C[(size_t)row * HH + tx * 8 + j]) = v;
        }
    }
}

// ---------------- layer init: h = bias + xw * dinv^2  (self-loop term, no atomics) ----------------
__global__ void layer_init_k(const float* __restrict__ xw, const float* __restrict__ bias,
                             const float* __restrict__ dinv, float* __restrict__ h) {
    int idx = blockIdx.x * blockDim.x + threadIdx.x;   // over NN*32 float4 units
    if (idx >= NN * 32) return;
    int node = idx >> 5;
    int f4   = idx & 31;
    float d  = dinv[node];
    float d2 = d * d;
    float4 v = *reinterpret_cast<const float4*>(xw + (size_t)node * HH + f4 * 4);
    float4 b = *reinterpret_cast<const float4*>(bias + f4 * 4);
    float4 o;
    o.x = fmaf(v.x, d2, b.x); o.y = fmaf(v.y, d2, b.y);
    o.z = fmaf(v.z, d2, b.z); o.w = fmaf(v.w, d2, b.w);
    *reinterpret_cast<float4*>(h + (size_t)node * HH + f4 * 4) = o;
}

// ---------------- edge aggregation: h[c] += xw[r] * dinv[r]*dinv[c]  (warp per edge) ----------------
__global__ void edge_agg_k(const float* __restrict__ src, float* __restrict__ dst,
                           const int* __restrict__ row, const int* __restrict__ col,
                           const float* __restrict__ dinv) {
    int warpId = (blockIdx.x * blockDim.x + threadIdx.x) >> 5;
    int lane   = threadIdx.x & 31;
    if (warpId >= EE) return;
    int r = __ldg(&row[warpId]);
    int c = __ldg(&col[warpId]);
    float norm = __ldg(&dinv[r]) * __ldg(&dinv[c]);
    float4 v = *reinterpret_cast<const float4*>(src + (size_t)r * HH + lane * 4);
    v.x *= norm; v.y *= norm; v.z *= norm; v.w *= norm;
    float* d = dst + (size_t)c * HH + lane * 4;
    asm volatile("red.global.add.v4.f32 [%0], {%1,%2,%3,%4};"
                 :: "l"(d), "f"(v.x), "f"(v.y), "f"(v.z), "f"(v.w) : "memory");
}

// ---------------- pooling ----------------
__global__ void zero_pool_k(float* sums, float* cnt) {
    int i = blockIdx.x * blockDim.x + threadIdx.x;
    if (i < GG * HH) sums[i] = 0.0f;
    if (i < GG) cnt[i] = 0.0f;
}

__global__ void pool_k(const float* __restrict__ h, const int* __restrict__ batch,
                       float* __restrict__ sums, float* __restrict__ cnt) {
    int warpId = (blockIdx.x * blockDim.x + threadIdx.x) >> 5;
    int lane   = threadIdx.x & 31;
    if (warpId >= NN) return;
    int g = __ldg(&batch[warpId]);
    float4 v = *reinterpret_cast<const float4*>(h + (size_t)warpId * HH + lane * 4);
    v.x = fmaxf(v.x, 0.0f); v.y = fmaxf(v.y, 0.0f);            // relu fused here
    v.z = fmaxf(v.z, 0.0f); v.w = fmaxf(v.w, 0.0f);
    float* d = sums + (size_t)g * HH + lane * 4;
    asm volatile("red.global.add.v4.f32 [%0], {%1,%2,%3,%4};"
                 :: "l"(d), "f"(v.x), "f"(v.y), "f"(v.z), "f"(v.w) : "memory");
    if (lane == 0) atomicAdd(&cnt[g], 1.0f);
}

// ---------------- head: mean -> FC -> log_softmax  (1 warp per graph) ----------------
__global__ void head_k(const float* __restrict__ sums, const float* __restrict__ cnt,
                       const float* __restrict__ Wfc, const float* __restrict__ bfc,
                       float* __restrict__ out) {
    int g = blockIdx.x;
    int lane = threadIdx.x;
    float inv = 1.0f / fmaxf(cnt[g], 1.0f);
    float p[4];
    #pragma unroll
    for (int i = 0; i < 4; i++)
        p[i] = sums[(size_t)g * HH + lane * 4 + i] * inv;

    float logits[OUTD];
    #pragma unroll
    for (int o = 0; o < OUTD; o++) {
        float s = 0.0f;
        #pragma unroll
        for (int i = 0; i < 4; i++)
            s = fmaf(p[i], __ldg(&Wfc[(size_t)(lane * 4 + i) * OUTD + o]), s);
        #pragma unroll
        for (int off = 16; off > 0; off >>= 1)
            s += __shfl_xor_sync(0xffffffffu, s, off);
        logits[o] = s + __ldg(&bfc[o]);
    }
    if (lane == 0) {
        float m = logits[0];
        #pragma unroll
        for (int o = 1; o < OUTD; o++) m = fmaxf(m, logits[o]);
        float lse = 0.0f;
        #pragma unroll
        for (int o = 0; o < OUTD; o++) lse += expf(logits[o] - m);
        lse = logf(lse);
        #pragma unroll
        for (int o = 0; o < OUTD; o++)
            out[(size_t)g * OUTD + o] = logits[o] - m - lse;
    }
}

// ---------------- launcher ----------------
extern "C" void kernel_launch(void* const* d_in, const int* in_sizes, int n_in,
                              void* d_out, int out_size) {
    const float* x    = (const float*)d_in[0];
    const int*   ei   = (const int*)d_in[1];     // [2, E]: row = ei[0:E], col = ei[E:2E]
    const int*   batch= (const int*)d_in[2];
    const float* W1   = (const float*)d_in[3];
    const float* b1   = (const float*)d_in[4];
    const float* W2   = (const float*)d_in[5];
    const float* b2   = (const float*)d_in[6];
    const float* Wfc  = (const float*)d_in[7];
    const float* bfc  = (const float*)d_in[8];
    float* out = (float*)d_out;

    const int* row = ei;
    const int* col = ei + EE;

    float* bufA = nullptr; cudaGetSymbolAddress((void**)&bufA, g_bufA);
    float* bufB = nullptr; cudaGetSymbolAddress((void**)&bufB, g_bufB);
    float* dinv = nullptr; cudaGetSymbolAddress((void**)&dinv, g_dinv);
    float* sums = nullptr; cudaGetSymbolAddress((void**)&sums, g_sums);
    float* cnt  = nullptr; cudaGetSymbolAddress((void**)&cnt,  g_cnt);

    const int T = 256;

    // degrees -> dinv (dinv buffer doubles as deg)
    deg_init_k<<<(NN + T - 1) / T, T>>>(dinv);
    deg_edges_k<<<(EE + T - 1) / T, T>>>(col, dinv);
    dinv_k<<<(NN + T - 1) / T, T>>>(dinv);

    // layer 1: xw = x @ W1 ; h1 = b1 + self + edge-agg
    gemm_k<<<NN / 64, T>>>(x, W1, bufA, 0);
    layer_init_k<<<(NN * 32 + T - 1) / T, T>>>(bufA, b1, dinv, bufB);
    edge_agg_k<<<(EE * 32 + T - 1) / T, T>>>(bufA, bufB, row, col, dinv);

    // layer 2: xw = relu(h1) @ W2 ; h2 = b2 + self + edge-agg
    gemm_k<<<NN / 64, T>>>(bufB, W2, bufA, 1);
    layer_init_k<<<(NN * 32 + T - 1) / T, T>>>(bufA, b2, dinv, bufB);
    edge_agg_k<<<(EE * 32 + T - 1) / T, T>>>(bufA, bufB, row, col, dinv);

    // mean pool (relu fused) -> FC -> log_softmax
    zero_pool_k<<<(GG * HH + T - 1) / T, T>>>(sums, cnt);
    pool_k<<<(NN * 32 + T - 1) / T, T>>>(bufB, batch, sums, cnt);
    head_k<<<GG, 32>>>(sums, cnt, Wfc, bfc, out);
}

// round 4
// speedup vs baseline: 1.1564x; 1.1564x over previous
#include <cuda_runtime.h>
#include <cuda_bf16.h>
#include <cstdint>

#define NN     40000
#define EE     640000
#define HH     128
#define GG     256
#define OUTD   10

// ---------------- scratch (no allocations allowed) ----------------
__device__ float g_bufA[(size_t)NN * HH];   // xw
__device__ float g_bufB[(size_t)NN * HH];   // h
__device__ float g_dinv[NN];
__device__ float g_sums[GG * HH];
__device__ float g_cnt[GG];

// ---------------- cp.async helpers ----------------
__device__ __forceinline__ void cp_async16(void* smem, const void* gmem) {
    unsigned s = (unsigned)__cvta_generic_to_shared(smem);
    asm volatile("cp.async.ca.shared.global [%0], [%1], 16;" :: "r"(s), "l"(gmem));
}
__device__ __forceinline__ void cp_commit() {
    asm volatile("cp.async.commit_group;" ::: "memory");
}
template <int N>
__device__ __forceinline__ void cp_wait() {
    asm volatile("cp.async.wait_group %0;" :: "n"(N) : "memory");
}

// ---------------- degree / norm ----------------
__global__ void deg_init_k(float* deg) {
    int i = blockIdx.x * blockDim.x + threadIdx.x;
    if (i < NN) deg[i] = 1.0f;                 // self-loop
}

__global__ void deg_edges_k(const int* __restrict__ col, float* deg) {
    int e = blockIdx.x * blockDim.x + threadIdx.x;
    if (e < EE) atomicAdd(&deg[col[e]], 1.0f);
}

__global__ void dinv_k(float* dinv) {
    int i = blockIdx.x * blockDim.x + threadIdx.x;
    if (i < NN) dinv[i] = rsqrtf(dinv[i]);     // deg >= 1 always
}

// ---------------- fused GEMM: xw = (relu?)A @ W ; h = bias + xw * dinv^2 ----------------
// 64x128 tile, 128 threads, 8x8 per thread, cp.async double-buffered k-chunks of 16.
template <int RELU>
__global__ __launch_bounds__(128)
void gemm_fused_k(const float* __restrict__ A, const float* __restrict__ W,
                  const float* __restrict__ bias, const float* __restrict__ dinv,
                  float* __restrict__ xw, float* __restrict__ h) {
    __shared__ float As[2][64][20];    // padded (20 keeps 16B alignment, conflict-free)
    __shared__ float Ws[2][16][128];

    const int tid = threadIdx.x;
    const int tx  = tid & 15;          // col group: cols tx*8 .. tx*8+7
    const int ty  = tid >> 4;          // row group: rows ty*8 .. ty*8+7
    const int rowBase = blockIdx.x * 64;

    float acc[8][8];
    #pragma unroll
    for (int i = 0; i < 8; i++)
        #pragma unroll
        for (int j = 0; j < 8; j++) acc[i][j] = 0.0f;

    // chunk loader: As 256 float4 (2/thread), Ws 512 float4 (4/thread)
    auto loadChunk = [&](int kc, int stage) {
        int k0 = kc * 16;
        #pragma unroll
        for (int i = 0; i < 2; i++) {
            int id = tid + i * 128;
            int r  = id >> 2;
            int c4 = (id & 3) * 4;
            cp_async16(&As[stage][r][c4],
                       &A[(size_t)(rowBase + r) * HH + k0 + c4]);
        }
        #pragma unroll
        for (int i = 0; i < 4; i++) {
            int id = tid + i * 128;
            int r  = id >> 5;
            int c  = (id & 31) * 4;
            cp_async16(&Ws[stage][r][c], &W[(size_t)(k0 + r) * HH + c]);
        }
        cp_commit();
    };

    loadChunk(0, 0);
    #pragma unroll 1
    for (int kc = 0; kc < 8; kc++) {
        int stage = kc & 1;
        if (kc < 7) { loadChunk(kc + 1, stage ^ 1); cp_wait<1>(); }
        else        { cp_wait<0>(); }
        __syncthreads();

        #pragma unroll
        for (int kk = 0; kk < 16; kk++) {
            float a[8], b[8];
            #pragma unroll
            for (int i = 0; i < 8; i++) {
                float v = As[stage][ty * 8 + i][kk];   // broadcast within half-warp
                a[i] = RELU ? fmaxf(v, 0.0f) : v;
            }
            float4 b0 = *reinterpret_cast<const float4*>(&Ws[stage][kk][tx * 8]);
            float4 b1 = *reinterpret_cast<const float4*>(&Ws[stage][kk][tx * 8 + 4]);
            b[0] = b0.x; b[1] = b0.y; b[2] = b0.z; b[3] = b0.w;
            b[4] = b1.x; b[5] = b1.y; b[6] = b1.z; b[7] = b1.w;
            #pragma unroll
            for (int i = 0; i < 8; i++)
                #pragma unroll
                for (int j = 0; j < 8; j++)
                    acc[i][j] = fmaf(a[i], b[j], acc[i][j]);
        }
        __syncthreads();
    }

    // epilogue: write xw and h = bias + xw * dinv^2  (layer_init fused)
    float4 bi0 = *reinterpret_cast<const float4*>(&bias[tx * 8]);
    float4 bi1 = *reinterpret_cast<const float4*>(&bias[tx * 8 + 4]);
    #pragma unroll
    for (int i = 0; i < 8; i++) {
        int row = rowBase + ty * 8 + i;
        float d  = __ldg(&dinv[row]);
        float d2 = d * d;
        float4 v0 = make_float4(acc[i][0], acc[i][1], acc[i][2], acc[i][3]);
        float4 v1 = make_float4(acc[i][4], acc[i][5], acc[i][6], acc[i][7]);
        *reinterpret_cast<float4*>(&xw[(size_t)row * HH + tx * 8])     = v0;
        *reinterpret_cast<float4*>(&xw[(size_t)row * HH + tx * 8 + 4]) = v1;
        float4 h0, h1;
        h0.x = fmaf(v0.x, d2, bi0.x); h0.y = fmaf(v0.y, d2, bi0.y);
        h0.z = fmaf(v0.z, d2, bi0.z); h0.w = fmaf(v0.w, d2, bi0.w);
        h1.x = fmaf(v1.x, d2, bi1.x); h1.y = fmaf(v1.y, d2, bi1.y);
        h1.z = fmaf(v1.z, d2, bi1.z); h1.w = fmaf(v1.w, d2, bi1.w);
        *reinterpret_cast<float4*>(&h[(size_t)row * HH + tx * 8])     = h0;
        *reinterpret_cast<float4*>(&h[(size_t)row * HH + tx * 8 + 4]) = h1;
    }
}

// ---------------- edge aggregation: h[c] += xw[r] * dinv[r]*dinv[c]  (warp per edge) ----------------
__global__ void edge_agg_k(const float* __restrict__ src, float* __restrict__ dst,
                           const int* __restrict__ row, const int* __restrict__ col,
                           const float* __restrict__ dinv) {
    int warpId = (blockIdx.x * blockDim.x + threadIdx.x) >> 5;
    int lane   = threadIdx.x & 31;
    if (warpId >= EE) return;
    int r = __ldg(&row[warpId]);
    int c = __ldg(&col[warpId]);
    float norm = __ldg(&dinv[r]) * __ldg(&dinv[c]);
    float4 v = *reinterpret_cast<const float4*>(src + (size_t)r * HH + lane * 4);
    v.x *= norm; v.y *= norm; v.z *= norm; v.w *= norm;
    float* d = dst + (size_t)c * HH + lane * 4;
    asm volatile("red.global.add.v4.f32 [%0], {%1,%2,%3,%4};"
                 :: "l"(d), "f"(v.x), "f"(v.y), "f"(v.z), "f"(v.w) : "memory");
}

// ---------------- pooling ----------------
__global__ void zero_pool_k(float* sums, float* cnt) {
    int i = blockIdx.x * blockDim.x + threadIdx.x;
    if (i < GG * HH) sums[i] = 0.0f;
    if (i < GG) cnt[i] = 0.0f;
}

__global__ void pool_k(const float* __restrict__ h, const int* __restrict__ batch,
                       float* __restrict__ sums, float* __restrict__ cnt) {
    int warpId = (blockIdx.x * blockDim.x + threadIdx.x) >> 5;
    int lane   = threadIdx.x & 31;
    if (warpId >= NN) return;
    int g = __ldg(&batch[warpId]);
    float4 v = *reinterpret_cast<const float4*>(h + (size_t)warpId * HH + lane * 4);
    v.x = fmaxf(v.x, 0.0f); v.y = fmaxf(v.y, 0.0f);            // relu fused
    v.z = fmaxf(v.z, 0.0f); v.w = fmaxf(v.w, 0.0f);
    float* d = sums + (size_t)g * HH + lane * 4;
    asm volatile("red.global.add.v4.f32 [%0], {%1,%2,%3,%4};"
                 :: "l"(d), "f"(v.x), "f"(v.y), "f"(v.z), "f"(v.w) : "memory");
    if (lane == 0) atomicAdd(&cnt[g], 1.0f);
}

// ---------------- head: mean -> FC -> log_softmax  (1 warp per graph) ----------------
__global__ void head_k(const float* __restrict__ sums, const float* __restrict__ cnt,
                       const float* __restrict__ Wfc, const float* __restrict__ bfc,
                       float* __restrict__ out) {
    int g = blockIdx.x;
    int lane = threadIdx.x;
    float inv = 1.0f / fmaxf(cnt[g], 1.0f);
    float p[4];
    #pragma unroll
    for (int i = 0; i < 4; i++)
        p[i] = sums[(size_t)g * HH + lane * 4 + i] * inv;

    float logits[OUTD];
    #pragma unroll
    for (int o = 0; o < OUTD; o++) {
        float s = 0.0f;
        #pragma unroll
        for (int i = 0; i < 4; i++)
            s = fmaf(p[i], __ldg(&Wfc[(size_t)(lane * 4 + i) * OUTD + o]), s);
        #pragma unroll
        for (int off = 16; off > 0; off >>= 1)
            s += __shfl_xor_sync(0xffffffffu, s, off);
        logits[o] = s + __ldg(&bfc[o]);
    }
    if (lane == 0) {
        float m = logits[0];
        #pragma unroll
        for (int o = 1; o < OUTD; o++) m = fmaxf(m, logits[o]);
        float lse = 0.0f;
        #pragma unroll
        for (int o = 0; o < OUTD; o++) lse += expf(logits[o] - m);
        lse = logf(lse);
        #pragma unroll
        for (int o = 0; o < OUTD; o++)
            out[(size_t)g * OUTD + o] = logits[o] - m - lse;
    }
}

// ---------------- launcher ----------------
extern "C" void kernel_launch(void* const* d_in, const int* in_sizes, int n_in,
                              void* d_out, int out_size) {
    const float* x    = (const float*)d_in[0];
    const int*   ei   = (const int*)d_in[1];     // [2, E]
    const int*   batch= (const int*)d_in[2];
    const float* W1   = (const float*)d_in[3];
    const float* b1   = (const float*)d_in[4];
    const float* W2   = (const float*)d_in[5];
    const float* b2   = (const float*)d_in[6];
    const float* Wfc  = (const float*)d_in[7];
    const float* bfc  = (const float*)d_in[8];
    float* out = (float*)d_out;

    const int* row = ei;
    const int* col = ei + EE;

    float* bufA = nullptr; cudaGetSymbolAddress((void**)&bufA, g_bufA);
    float* bufB = nullptr; cudaGetSymbolAddress((void**)&bufB, g_bufB);
    float* dinv = nullptr; cudaGetSymbolAddress((void**)&dinv, g_dinv);
    float* sums = nullptr; cudaGetSymbolAddress((void**)&sums, g_sums);
    float* cnt  = nullptr; cudaGetSymbolAddress((void**)&cnt,  g_cnt);

    const int T = 256;

    // degrees -> dinv
    deg_init_k<<<(NN + T - 1) / T, T>>>(dinv);
    deg_edges_k<<<(EE + T - 1) / T, T>>>(col, dinv);
    dinv_k<<<(NN + T - 1) / T, T>>>(dinv);

    // layer 1: fused gemm (xw=bufA, h-init=bufB), then edge aggregation
    gemm_fused_k<0><<<NN / 64, 128>>>(x, W1, b1, dinv, bufA, bufB);
    edge_agg_k<<<(EE * 32 + T - 1) / T, T>>>(bufA, bufB, row, col, dinv);

    // layer 2: fused gemm with relu on input
    gemm_fused_k<1><<<NN / 64, 128>>>(bufB, W2, b2, dinv, bufA, bufB);
    edge_agg_k<<<(EE * 32 + T - 1) / T, T>>>(bufA, bufB, row, col, dinv);

    // mean pool (relu fused) -> FC -> log_softmax
    zero_pool_k<<<(GG * HH + T - 1) / T, T>>>(sums, cnt);
    pool_k<<<(NN * 32 + T - 1) / T, T>>>(bufB, batch, sums, cnt);
    head_k<<<GG, 32>>>(sums, cnt, Wfc, bfc, out);
}

// round 6
// speedup vs baseline: 1.5163x; 1.3112x over previous
#include <cuda_runtime.h>
#include <cuda_bf16.h>
#include <cstdint>

#define NN     40000
#define EE     640000
#define HH     128
#define GG     256
#define OUTD   10

// ---------------- scratch (no allocations allowed) ----------------
__device__ float g_bufA[(size_t)NN * HH];   // xw
__device__ float g_bufB[(size_t)NN * HH];   // h1
__device__ float g_dinv[NN];
__device__ int   g_degi[NN];
__device__ int   g_off[NN + 1];
__device__ int   g_cur[NN];
__device__ int   g_csrc[EE];                // edge sources grouped by destination
__device__ float g_sums[GG * HH];
__device__ float g_cnt[GG];

// ---------------- cp.async helpers ----------------
__device__ __forceinline__ void cp_async16(void* smem, const void* gmem) {
    unsigned s = (unsigned)__cvta_generic_to_shared(smem);
    asm volatile("cp.async.ca.shared.global [%0], [%1], 16;" :: "r"(s), "l"(gmem));
}
__device__ __forceinline__ void cp_commit() {
    asm volatile("cp.async.commit_group;" ::: "memory");
}
template <int N>
__device__ __forceinline__ void cp_wait() {
    asm volatile("cp.async.wait_group %0;" :: "n"(N) : "memory");
}

// ---------------- setup ----------------
__global__ void zero_k(int* degi, int* cur, float* sums, float* cnt) {
    int i = blockIdx.x * blockDim.x + threadIdx.x;
    if (i < NN) { degi[i] = 0; cur[i] = 0; }
    if (i < GG * HH) sums[i] = 0.0f;
    if (i < GG) cnt[i] = 0.0f;
}

__global__ void count_k(const int* __restrict__ col, int* degi) {
    int e = blockIdx.x * blockDim.x + threadIdx.x;
    if (e < EE) atomicAdd(&degi[col[e]], 1);
}

__global__ void dinv_cnt_k(const int* __restrict__ degi, float* __restrict__ dinv,
                           const int* __restrict__ batch, float* cnt) {
    int i = blockIdx.x * blockDim.x + threadIdx.x;
    if (i < NN) {
        dinv[i] = rsqrtf((float)(degi[i] + 1));   // +1 self-loop
        atomicAdd(&cnt[batch[i]], 1.0f);
    }
}

// single-block exclusive scan -> off[0..NN], off[0]=0
__global__ __launch_bounds__(1024)
void scan_k(const int* __restrict__ deg, int* __restrict__ off) {
    __shared__ int wsum[32];
    __shared__ int carry;
    int tid = threadIdx.x, lane = tid & 31, wid = tid >> 5;
    if (tid == 0) { carry = 0; off[0] = 0; }
    __syncthreads();
    for (int base = 0; base < NN; base += 1024) {
        int i = base + tid;
        int v = (i < NN) ? deg[i] : 0;
        int x = v;
        #pragma unroll
        for (int o = 1; o < 32; o <<= 1) {
            int t = __shfl_up_sync(0xffffffffu, x, o);
            if (lane >= o) x += t;
        }
        if (lane == 31) wsum[wid] = x;
        __syncthreads();
        if (wid == 0) {
            int y = wsum[lane];
            #pragma unroll
            for (int o = 1; o < 32; o <<= 1) {
                int t = __shfl_up_sync(0xffffffffu, y, o);
                if (lane >= o) y += t;
            }
            wsum[lane] = y;
        }
        __syncthreads();
        int incl = x + (wid ? wsum[wid - 1] : 0) + carry;
        if (i < NN) off[i + 1] = incl;
        __syncthreads();
        if (tid == 1023) carry = incl;
        __syncthreads();
    }
}

__global__ void scatter_k(const int* __restrict__ row, const int* __restrict__ col,
                          const int* __restrict__ off, int* cur, int* __restrict__ csrc) {
    int e = blockIdx.x * blockDim.x + threadIdx.x;
    if (e >= EE) return;
    int c = col[e];
    int pos = off[c] + atomicAdd(&cur[c], 1);
    csrc[pos] = row[e];
}

// ---------------- GEMM: xw = (relu?)A @ W  (64x128 tile, 128 thr, 8x8/thr) ----------------
template <int RELU>
__global__ __launch_bounds__(128)
void gemm_k(const float* __restrict__ A, const float* __restrict__ W,
            float* __restrict__ xw) {
    __shared__ float As[2][64][20];
    __shared__ float Ws[2][16][128];

    const int tid = threadIdx.x;
    const int tx  = tid & 15;
    const int ty  = tid >> 4;
    const int rowBase = blockIdx.x * 64;

    float acc[8][8];
    #pragma unroll
    for (int i = 0; i < 8; i++)
        #pragma unroll
        for (int j = 0; j < 8; j++) acc[i][j] = 0.0f;

    auto loadChunk = [&](int kc, int stage) {
        int k0 = kc * 16;
        #pragma unroll
        for (int i = 0; i < 2; i++) {
            int id = tid + i * 128;
            int r  = id >> 2;
            int c4 = (id & 3) * 4;
            cp_async16(&As[stage][r][c4], &A[(size_t)(rowBase + r) * HH + k0 + c4]);
        }
        #pragma unroll
        for (int i = 0; i < 4; i++) {
            int id = tid + i * 128;
            int r  = id >> 5;
            int c  = (id & 31) * 4;
            cp_async16(&Ws[stage][r][c], &W[(size_t)(k0 + r) * HH + c]);
        }
        cp_commit();
    };

    loadChunk(0, 0);
    #pragma unroll 1
    for (int kc = 0; kc < 8; kc++) {
        int stage = kc & 1;
        if (kc < 7) { loadChunk(kc + 1, stage ^ 1); cp_wait<1>(); }
        else        { cp_wait<0>(); }
        __syncthreads();

        #pragma unroll
        for (int kk = 0; kk < 16; kk++) {
            float a[8], b[8];
            #pragma unroll
            for (int i = 0; i < 8; i++) {
                float v = As[stage][ty * 8 + i][kk];
                a[i] = RELU ? fmaxf(v, 0.0f) : v;
            }
            float4 b0 = *reinterpret_cast<const float4*>(&Ws[stage][kk][tx * 8]);
            float4 b1 = *reinterpret_cast<const float4*>(&Ws[stage][kk][tx * 8 + 4]);
            b[0] = b0.x; b[1] = b0.y; b[2] = b0.z; b[3] = b0.w;
            b[4] = b1.x; b[5] = b1.y; b[6] = b1.z; b[7] = b1.w;
            #pragma unroll
            for (int i = 0; i < 8; i++)
                #pragma unroll
                for (int j = 0; j < 8; j++)
                    acc[i][j] = fmaf(a[i], b[j], acc[i][j]);
        }
        __syncthreads();
    }

    #pragma unroll
    for (int i = 0; i < 8; i++) {
        int row = rowBase + ty * 8 + i;
        float4 v0 = make_float4(acc[i][0], acc[i][1], acc[i][2], acc[i][3]);
        float4 v1 = make_float4(acc[i][4], acc[i][5], acc[i][6], acc[i][7]);
        *reinterpret_cast<float4*>(&xw[(size_t)row * HH + tx * 8])     = v0;
        *reinterpret_cast<float4*>(&xw[(size_t)row * HH + tx * 8 + 4]) = v1;
    }
}

// ---------------- node aggregation (warp per node, register accumulate) ----------------
// h[n] = (xw[n]*dinv[n] + sum_{src in in(n)} xw[src]*dinv[src]) * dinv[n] + bias
// POOL=0: write h.   POOL=1: relu then red.add into sums[batch[n]].
template <int POOL>
__global__ __launch_bounds__(256)
void agg_node_k(const float* __restrict__ xw, const float* __restrict__ dinv,
                const int* __restrict__ off, const int* __restrict__ csrc,
                const float* __restrict__ bias, float* __restrict__ h,
                const int* __restrict__ batch, float* __restrict__ sums) {
    int n    = (blockIdx.x * blockDim.x + threadIdx.x) >> 5;
    int lane = threadIdx.x & 31;
    if (n >= NN) return;

    float dn = __ldg(&dinv[n]);
    float4 acc = *reinterpret_cast<const float4*>(xw + (size_t)n * HH + lane * 4);
    acc.x *= dn; acc.y *= dn; acc.z *= dn; acc.w *= dn;

    int p = __ldg(&off[n]);
    int e = __ldg(&off[n + 1]);

    for (; p + 1 < e; p += 2) {                 // 2-deep for MLP
        int s0 = __ldg(&csrc[p]);
        int s1 = __ldg(&csrc[p + 1]);
        float w0 = __ldg(&dinv[s0]);
        float w1 = __ldg(&dinv[s1]);
        float4 v0 = *reinterpret_cast<const float4*>(xw + (size_t)s0 * HH + lane * 4);
        float4 v1 = *reinterpret_cast<const float4*>(xw + (size_t)s1 * HH + lane * 4);
        acc.x += v0.x * w0 + v1.x * w1;
        acc.y += v0.y * w0 + v1.y * w1;
        acc.z += v0.z * w0 + v1.z * w1;
        acc.w += v0.w * w0 + v1.w * w1;
    }
    if (p < e) {
        int s0 = __ldg(&csrc[p]);
        float w0 = __ldg(&dinv[s0]);
        float4 v0 = *reinterpret_cast<const float4*>(xw + (size_t)s0 * HH + lane * 4);
        acc.x += v0.x * w0; acc.y += v0.y * w0;
        acc.z += v0.z * w0; acc.w += v0.w * w0;
    }

    float4 b = *reinterpret_cast<const float4*>(bias + lane * 4);
    float4 o;
    o.x = fmaf(acc.x, dn, b.x); o.y = fmaf(acc.y, dn, b.y);
    o.z = fmaf(acc.z, dn, b.z); o.w = fmaf(acc.w, dn, b.w);

    if (POOL) {
        o.x = fmaxf(o.x, 0.0f); o.y = fmaxf(o.y, 0.0f);
        o.z = fmaxf(o.z, 0.0f); o.w = fmaxf(o.w, 0.0f);
        int g = __ldg(&batch[n]);
        float* d = sums + (size_t)g * HH + lane * 4;
        asm volatile("red.global.add.v4.f32 [%0], {%1,%2,%3,%4};"
                     :: "l"(d), "f"(o.x), "f"(o.y), "f"(o.z), "f"(o.w) : "memory");
    } else {
        *reinterpret_cast<float4*>(h + (size_t)n * HH + lane * 4) = o;
    }
}

// ---------------- head: mean -> FC -> log_softmax  (1 warp per graph) ----------------
__global__ void head_k(const float* __restrict__ sums, const float* __restrict__ cnt,
                       const float* __restrict__ Wfc, const float* __restrict__ bfc,
                       float* __restrict__ out) {
    int g = blockIdx.x;
    int lane = threadIdx.x;
    float inv = 1.0f / fmaxf(cnt[g], 1.0f);
    float p[4];
    #pragma unroll
    for (int i = 0; i < 4; i++)
        p[i] = sums[(size_t)g * HH + lane * 4 + i] * inv;

    float logits[OUTD];
    #pragma unroll
    for (int o = 0; o < OUTD; o++) {
        float s = 0.0f;
        #pragma unroll
        for (int i = 0; i < 4; i++)
            s = fmaf(p[i], __ldg(&Wfc[(size_t)(lane * 4 + i) * OUTD + o]), s);
        #pragma unroll
        for (int off = 16; off > 0; off >>= 1)
            s += __shfl_xor_sync(0xffffffffu, s, off);
        logits[o] = s + __ldg(&bfc[o]);
    }
    if (lane == 0) {
        float m = logits[0];
        #pragma unroll
        for (int o = 1; o < OUTD; o++) m = fmaxf(m, logits[o]);
        float lse = 0.0f;
        #pragma unroll
        for (int o = 0; o < OUTD; o++) lse += expf(logits[o] - m);
        lse = logf(lse);
        #pragma unroll
        for (int o = 0; o < OUTD; o++)
            out[(size_t)g * OUTD + o] = logits[o] - m - lse;
    }
}

// ---------------- launcher ----------------
extern "C" void kernel_launch(void* const* d_in, const int* in_sizes, int n_in,
                              void* d_out, int out_size) {
    const float* x    = (const float*)d_in[0];
    const int*   ei   = (const int*)d_in[1];
    const int*   batch= (const int*)d_in[2];
    const float* W1   = (const float*)d_in[3];
    const float* b1   = (const float*)d_in[4];
    const float* W2   = (const float*)d_in[5];
    const float* b2   = (const float*)d_in[6];
    const float* Wfc  = (const float*)d_in[7];
    const float* bfc  = (const float*)d_in[8];
    float* out = (float*)d_out;

    const int* row = ei;
    const int* col = ei + EE;

    float* bufA = nullptr; cudaGetSymbolAddress((void**)&bufA, g_bufA);
    float* bufB = nullptr; cudaGetSymbolAddress((void**)&bufB, g_bufB);
    float* dinv = nullptr; cudaGetSymbolAddress((void**)&dinv, g_dinv);
    int*   degi = nullptr; cudaGetSymbolAddress((void**)&degi, g_degi);
    int*   off  = nullptr; cudaGetSymbolAddress((void**)&off,  g_off);
    int*   cur  = nullptr; cudaGetSymbolAddress((void**)&cur,  g_cur);
    int*   csrc = nullptr; cudaGetSymbolAddress((void**)&csrc, g_csrc);
    float* sums = nullptr; cudaGetSymbolAddress((void**)&sums, g_sums);
    float* cnt  = nullptr; cudaGetSymbolAddress((void**)&cnt,  g_cnt);

    const int T = 256;

    // setup: degrees, dinv, graph-size histogram, CSC build
    zero_k<<<(NN + T - 1) / T, T>>>(degi, cur, sums, cnt);
    count_k<<<(EE + T - 1) / T, T>>>(col, degi);
    dinv_cnt_k<<<(NN + T - 1) / T, T>>>(degi, dinv, batch, cnt);
    scan_k<<<1, 1024>>>(degi, off);
    scatter_k<<<(EE + T - 1) / T, T>>>(row, col, off, cur, csrc);

    // layer 1
    gemm_k<0><<<NN / 64, 128>>>(x, W1, bufA);
    agg_node_k<0><<<(NN * 32 + T - 1) / T, T>>>(bufA, dinv, off, csrc, b1, bufB, nullptr, nullptr);

    // layer 2 (pool fused into aggregation)
    gemm_k<1><<<NN / 64, 128>>>(bufB, W2, bufA);
    agg_node_k<1><<<(NN * 32 + T - 1) / T, T>>>(bufA, dinv, off, csrc, b2, nullptr, batch, sums);

    // head
    head_k<<<GG, 32>>>(sums, cnt, Wfc, bfc, out);
}

// round 8
// speedup vs baseline: 1.7373x; 1.1457x over previous
#include <cuda_runtime.h>
#include <cuda_bf16.h>
#include <cstdint>

#define NN     40000
#define EE     640000
#define HH     128
#define GG     256
#define OUTD   10

#define SCAN_T 1024
#define SCAN_B ((NN + SCAN_T - 1) / SCAN_T)   // 40 blocks

// ---------------- scratch (no allocations allowed) ----------------
__device__ float g_bufA[(size_t)NN * HH];   // xw
__device__ float g_bufB[(size_t)NN * HH];   // h1
__device__ float g_dinv[NN];
__device__ int   g_degi[NN];
__device__ int   g_off[NN + 1];
__device__ int   g_cur[NN];
__device__ int   g_csrc[EE];                // edge sources grouped by destination
__device__ int   g_bsum[SCAN_B];
__device__ float g_sums[GG * HH];
__device__ float g_cnt[GG];

// ---------------- cp.async helpers ----------------
__device__ __forceinline__ void cp_async16(void* smem, const void* gmem) {
    unsigned s = (unsigned)__cvta_generic_to_shared(smem);
    asm volatile("cp.async.ca.shared.global [%0], [%1], 16;" :: "r"(s), "l"(gmem));
}
__device__ __forceinline__ void cp_commit() {
    asm volatile("cp.async.commit_group;" ::: "memory");
}
template <int N>
__device__ __forceinline__ void cp_wait() {
    asm volatile("cp.async.wait_group %0;" :: "n"(N) : "memory");
}

// ---------------- setup ----------------
__global__ void zero_k(int* degi, int* cur, float* sums, float* cnt) {
    int i = blockIdx.x * blockDim.x + threadIdx.x;
    if (i < NN) { degi[i] = 0; cur[i] = 0; }
    if (i < GG * HH) sums[i] = 0.0f;
    if (i < GG) cnt[i] = 0.0f;
}

__global__ void count_k(const int* __restrict__ col, int* degi) {
    int e = blockIdx.x * blockDim.x + threadIdx.x;
    if (e < EE) atomicAdd(&degi[col[e]], 1);
}

__global__ void dinv_cnt_k(const int* __restrict__ degi, float* __restrict__ dinv,
                           const int* __restrict__ batch, float* cnt) {
    int i = blockIdx.x * blockDim.x + threadIdx.x;
    if (i < NN) {
        dinv[i] = rsqrtf((float)(degi[i] + 1));   // +1 self-loop
        atomicAdd(&cnt[batch[i]], 1.0f);
    }
}

// ---------------- multi-block exclusive scan of degi -> off ----------------
// phase 1: per-block inclusive scan, write to off[i+1] (no cross-block carry), block total -> bsum
__global__ __launch_bounds__(SCAN_T)
void scan1_k(const int* __restrict__ deg, int* __restrict__ off, int* __restrict__ bsum) {
    __shared__ int wsum[32];
    int tid = threadIdx.x, lane = tid & 31, wid = tid >> 5;
    int i = blockIdx.x * SCAN_T + tid;
    int v = (i < NN) ? deg[i] : 0;
    int x = v;
    #pragma unroll
    for (int o = 1; o < 32; o <<= 1) {
        int t = __shfl_up_sync(0xffffffffu, x, o);
        if (lane >= o) x += t;
    }
    if (lane == 31) wsum[wid] = x;
    __syncthreads();
    if (wid == 0) {
        int y = wsum[lane];
        #pragma unroll
        for (int o = 1; o < 32; o <<= 1) {
            int t = __shfl_up_sync(0xffffffffu, y, o);
            if (lane >= o) y += t;
        }
        wsum[lane] = y;
    }
    __syncthreads();
    int incl = x + (wid ? wsum[wid - 1] : 0);
    if (i < NN) off[i + 1] = incl;
    if (tid == SCAN_T - 1) bsum[blockIdx.x] = incl;
}

// phase 2: scan the block totals (SCAN_B <= 64) -> exclusive prefix in-place
__global__ void scan2_k(int* __restrict__ bsum) {
    int lane = threadIdx.x & 31;
    int i0 = lane, i1 = lane + 32;
    int v0 = (i0 < SCAN_B) ? bsum[i0] : 0;
    int v1 = (i1 < SCAN_B) ? bsum[i1] : 0;
    int x0 = v0;
    #pragma unroll
    for (int o = 1; o < 32; o <<= 1) {
        int t = __shfl_up_sync(0xffffffffu, x0, o);
        if (lane >= o) x0 += t;
    }
    int tot0 = __shfl_sync(0xffffffffu, x0, 31);
    int x1 = v1;
    #pragma unroll
    for (int o = 1; o < 32; o <<= 1) {
        int t = __shfl_up_sync(0xffffffffu, x1, o);
        if (lane >= o) x1 += t;
    }
    if (i0 < SCAN_B) bsum[i0] = x0 - v0;                 // exclusive
    if (i1 < SCAN_B) bsum[i1] = x1 - v1 + tot0;
}

// phase 3: add block prefix
__global__ __launch_bounds__(SCAN_T)
void scan3_k(int* __restrict__ off, const int* __restrict__ bsum) {
    int i = blockIdx.x * SCAN_T + threadIdx.x;
    if (i == 0) off[0] = 0;
    if (i < NN) off[i + 1] += bsum[blockIdx.x];
}

__global__ void scatter_k(const int* __restrict__ row, const int* __restrict__ col,
                          const int* __restrict__ off, int* cur, int* __restrict__ csrc) {
    int e = blockIdx.x * blockDim.x + threadIdx.x;
    if (e >= EE) return;
    int c = col[e];
    int pos = off[c] + atomicAdd(&cur[c], 1);
    csrc[pos] = row[e];
}

// ---------------- GEMM: xw = (relu?)A @ W  (64x128 tile, 128 thr, 8x8/thr) ----------------
template <int RELU>
__global__ __launch_bounds__(128)
void gemm_k(const float* __restrict__ A, const float* __restrict__ W,
            float* __restrict__ xw) {
    __shared__ float As[2][64][20];
    __shared__ float Ws[2][16][128];

    const int tid = threadIdx.x;
    const int tx  = tid & 15;
    const int ty  = tid >> 4;
    const int rowBase = blockIdx.x * 64;

    float acc[8][8];
    #pragma unroll
    for (int i = 0; i < 8; i++)
        #pragma unroll
        for (int j = 0; j < 8; j++) acc[i][j] = 0.0f;

    auto loadChunk = [&](int kc, int stage) {
        int k0 = kc * 16;
        #pragma unroll
        for (int i = 0; i < 2; i++) {
            int id = tid + i * 128;
            int r  = id >> 2;
            int c4 = (id & 3) * 4;
            cp_async16(&As[stage][r][c4], &A[(size_t)(rowBase + r) * HH + k0 + c4]);
        }
        #pragma unroll
        for (int i = 0; i < 4; i++) {
            int id = tid + i * 128;
            int r  = id >> 5;
            int c  = (id & 31) * 4;
            cp_async16(&Ws[stage][r][c], &W[(size_t)(k0 + r) * HH + c]);
        }
        cp_commit();
    };

    loadChunk(0, 0);
    #pragma unroll 1
    for (int kc = 0; kc < 8; kc++) {
        int stage = kc & 1;
        if (kc < 7) { loadChunk(kc + 1, stage ^ 1); cp_wait<1>(); }
        else        { cp_wait<0>(); }
        __syncthreads();

        #pragma unroll
        for (int kk = 0; kk < 16; kk++) {
            float a[8], b[8];
            #pragma unroll
            for (int i = 0; i < 8; i++) {
                float v = As[stage][ty * 8 + i][kk];
                a[i] = RELU ? fmaxf(v, 0.0f) : v;
            }
            float4 b0 = *reinterpret_cast<const float4*>(&Ws[stage][kk][tx * 8]);
            float4 b1 = *reinterpret_cast<const float4*>(&Ws[stage][kk][tx * 8 + 4]);
            b[0] = b0.x; b[1] = b0.y; b[2] = b0.z; b[3] = b0.w;
            b[4] = b1.x; b[5] = b1.y; b[6] = b1.z; b[7] = b1.w;
            #pragma unroll
            for (int i = 0; i < 8; i++)
                #pragma unroll
                for (int j = 0; j < 8; j++)
                    acc[i][j] = fmaf(a[i], b[j], acc[i][j]);
        }
        __syncthreads();
    }

    #pragma unroll
    for (int i = 0; i < 8; i++) {
        int row = rowBase + ty * 8 + i;
        float4 v0 = make_float4(acc[i][0], acc[i][1], acc[i][2], acc[i][3]);
        float4 v1 = make_float4(acc[i][4], acc[i][5], acc[i][6], acc[i][7]);
        *reinterpret_cast<float4*>(&xw[(size_t)row * HH + tx * 8])     = v0;
        *reinterpret_cast<float4*>(&xw[(size_t)row * HH + tx * 8 + 4]) = v1;
    }
}

// ---------------- node aggregation (warp per node, register accumulate) ----------------
template <int POOL>
__global__ __launch_bounds__(256)
void agg_node_k(const float* __restrict__ xw, const float* __restrict__ dinv,
                const int* __restrict__ off, const int* __restrict__ csrc,
                const float* __restrict__ bias, float* __restrict__ h,
                const int* __restrict__ batch, float* __restrict__ sums) {
    int n    = (blockIdx.x * blockDim.x + threadIdx.x) >> 5;
    int lane = threadIdx.x & 31;
    if (n >= NN) return;

    float dn = __ldg(&dinv[n]);
    float4 acc = *reinterpret_cast<const float4*>(xw + (size_t)n * HH + lane * 4);
    acc.x *= dn; acc.y *= dn; acc.z *= dn; acc.w *= dn;

    int p = __ldg(&off[n]);
    int e = __ldg(&off[n + 1]);

    for (; p + 1 < e; p += 2) {
        int s0 = __ldg(&csrc[p]);
        int s1 = __ldg(&csrc[p + 1]);
        float w0 = __ldg(&dinv[s0]);
        float w1 = __ldg(&dinv[s1]);
        float4 v0 = *reinterpret_cast<const float4*>(xw + (size_t)s0 * HH + lane * 4);
        float4 v1 = *reinterpret_cast<const float4*>(xw + (size_t)s1 * HH + lane * 4);
        acc.x += v0.x * w0 + v1.x * w1;
        acc.y += v0.y * w0 + v1.y * w1;
        acc.z += v0.z * w0 + v1.z * w1;
        acc.w += v0.w * w0 + v1.w * w1;
    }
    if (p < e) {
        int s0 = __ldg(&csrc[p]);
        float w0 = __ldg(&dinv[s0]);
        float4 v0 = *reinterpret_cast<const float4*>(xw + (size_t)s0 * HH + lane * 4);
        acc.x += v0.x * w0; acc.y += v0.y * w0;
        acc.z += v0.z * w0; acc.w += v0.w * w0;
    }

    float4 b = *reinterpret_cast<const float4*>(bias + lane * 4);
    float4 o;
    o.x = fmaf(acc.x, dn, b.x); o.y = fmaf(acc.y, dn, b.y);
    o.z = fmaf(acc.z, dn, b.z); o.w = fmaf(acc.w, dn, b.w);

    if (POOL) {
        o.x = fmaxf(o.x, 0.0f); o.y = fmaxf(o.y, 0.0f);
        o.z = fmaxf(o.z, 0.0f); o.w = fmaxf(o.w, 0.0f);
        int g = __ldg(&batch[n]);
        float* d = sums + (size_t)g * HH + lane * 4;
        asm volatile("red.global.add.v4.f32 [%0], {%1,%2,%3,%4};"
                     :: "l"(d), "f"(o.x), "f"(o.y), "f"(o.z), "f"(o.w) : "memory");
    } else {
        *reinterpret_cast<float4*>(h + (size_t)n * HH + lane * 4) = o;
    }
}

// ---------------- head: mean -> FC -> log_softmax  (1 warp per graph) ----------------
__global__ void head_k(const float* __restrict__ sums, const float* __restrict__ cnt,
                       const float* __restrict__ Wfc, const float* __restrict__ bfc,
                       float* __restrict__ out) {
    int g = blockIdx.x;
    int lane = threadIdx.x;
    float inv = 1.0f / fmaxf(cnt[g], 1.0f);
    float p[4];
    #pragma unroll
    for (int i = 0; i < 4; i++)
        p[i] = sums[(size_t)g * HH + lane * 4 + i] * inv;

    float logits[OUTD];
    #pragma unroll
    for (int o = 0; o < OUTD; o++) {
        float s = 0.0f;
        #pragma unroll
        for (int i = 0; i < 4; i++)
            s = fmaf(p[i], __ldg(&Wfc[(size_t)(lane * 4 + i) * OUTD + o]), s);
        #pragma unroll
        for (int off = 16; off > 0; off >>= 1)
            s += __shfl_xor_sync(0xffffffffu, s, off);
        logits[o] = s + __ldg(&bfc[o]);
    }
    if (lane == 0) {
        float m = logits[0];
        #pragma unroll
        for (int o = 1; o < OUTD; o++) m = fmaxf(m, logits[o]);
        float lse = 0.0f;
        #pragma unroll
        for (int o = 0; o < OUTD; o++) lse += expf(logits[o] - m);
        lse = logf(lse);
        #pragma unroll
        for (int o = 0; o < OUTD; o++)
            out[(size_t)g * OUTD + o] = logits[o] - m - lse;
    }
}

// ---------------- launcher ----------------
extern "C" void kernel_launch(void* const* d_in, const int* in_sizes, int n_in,
                              void* d_out, int out_size) {
    const float* x    = (const float*)d_in[0];
    const int*   ei   = (const int*)d_in[1];
    const int*   batch= (const int*)d_in[2];
    const float* W1   = (const float*)d_in[3];
    const float* b1   = (const float*)d_in[4];
    const float* W2   = (const float*)d_in[5];
    const float* b2   = (const float*)d_in[6];
    const float* Wfc  = (const float*)d_in[7];
    const float* bfc  = (const float*)d_in[8];
    float* out = (float*)d_out;

    const int* row = ei;
    const int* col = ei + EE;

    float* bufA = nullptr; cudaGetSymbolAddress((void**)&bufA, g_bufA);
    float* bufB = nullptr; cudaGetSymbolAddress((void**)&bufB, g_bufB);
    float* dinv = nullptr; cudaGetSymbolAddress((void**)&dinv, g_dinv);
    int*   degi = nullptr; cudaGetSymbolAddress((void**)&degi, g_degi);
    int*   off  = nullptr; cudaGetSymbolAddress((void**)&off,  g_off);
    int*   cur  = nullptr; cudaGetSymbolAddress((void**)&cur,  g_cur);
    int*   csrc = nullptr; cudaGetSymbolAddress((void**)&csrc, g_csrc);
    int*   bsum = nullptr; cudaGetSymbolAddress((void**)&bsum, g_bsum);
    float* sums = nullptr; cudaGetSymbolAddress((void**)&sums, g_sums);
    float* cnt  = nullptr; cudaGetSymbolAddress((void**)&cnt,  g_cnt);

    const int T = 256;

    // setup: degrees, dinv, graph-size histogram, CSC build
    zero_k<<<(NN + T - 1) / T, T>>>(degi, cur, sums, cnt);
    count_k<<<(EE + T - 1) / T, T>>>(col, degi);
    dinv_cnt_k<<<(NN + T - 1) / T, T>>>(degi, dinv, batch, cnt);
    scan1_k<<<SCAN_B, SCAN_T>>>(degi, off, bsum);
    scan2_k<<<1, 32>>>(bsum);
    scan3_k<<<SCAN_B, SCAN_T>>>(off, bsum);
    scatter_k<<<(EE + T - 1) / T, T>>>(row, col, off, cur, csrc);

    // layer 1
    gemm_k<0><<<NN / 64, 128>>>(x, W1, bufA);
    agg_node_k<0><<<(NN * 32 + T - 1) / T, T>>>(bufA, dinv, off, csrc, b1, bufB, nullptr, nullptr);

    // layer 2 (pool fused into aggregation)
    gemm_k<1><<<NN / 64, 128>>>(bufB, W2, bufA);
    agg_node_k<1><<<(NN * 32 + T - 1) / T, T>>>(bufA, dinv, off, csrc, b2, nullptr, batch, sums);

    // head
    head_k<<<GG, 32>>>(sums, cnt, Wfc, bfc, out);
}

// round 11
// speedup vs baseline: 1.8756x; 1.0796x over previous
#include <cuda_runtime.h>
#include <cuda_bf16.h>
#include <cstdint>

#define NN     40000
#define EE     640000
#define HH     128
#define GG     256
#define OUTD   10

#define SCAN_T 1024
#define SCAN_B ((NN + SCAN_T - 1) / SCAN_T)   // 40 blocks

// GEMM (tensor-core) geometry
#define WS_STRIDE 136                          // 8 mod 32 -> conflict-free B frags
#define AS_STRIDE 36                           // 4 mod 32 -> conflict-free A frags
#define SMEM_W_FLOATS (128 * WS_STRIDE)
#define SMEM_A_FLOATS (128 * AS_STRIDE)
#define GEMM_SMEM_BYTES ((SMEM_W_FLOATS + 2 * SMEM_A_FLOATS) * 4)

// ---------------- scratch (no allocations allowed) ----------------
__device__ float g_bufA[(size_t)NN * HH];   // xw
__device__ float g_bufB[(size_t)NN * HH];   // h1
__device__ float g_dinv[NN];
__device__ int   g_degi[NN];
__device__ int   g_off[NN + 1];
__device__ int   g_cur[NN];
__device__ int   g_csrc[EE];
__device__ int   g_bsum[SCAN_B];
__device__ float g_sums[GG * HH];
__device__ float g_cnt[GG];

// ---------------- cp.async helpers ----------------
__device__ __forceinline__ void cp_async16(void* smem, const void* gmem) {
    unsigned s = (unsigned)__cvta_generic_to_shared(smem);
    asm volatile("cp.async.ca.shared.global [%0], [%1], 16;" :: "r"(s), "l"(gmem));
}
__device__ __forceinline__ void cp_commit() {
    asm volatile("cp.async.commit_group;" ::: "memory");
}
template <int N>
__device__ __forceinline__ void cp_wait() {
    asm volatile("cp.async.wait_group %0;" :: "n"(N) : "memory");
}

// ---------------- tf32 helpers ----------------
__device__ __forceinline__ unsigned f2tf32(float x) {
    unsigned r;
    asm("cvt.rna.tf32.f32 %0, %1;" : "=r"(r) : "f"(x));
    return r;
}
__device__ __forceinline__ void mma_tf32(float c[4], const unsigned a[4], const unsigned b[2]) {
    asm volatile(
        "mma.sync.aligned.m16n8k8.row.col.f32.tf32.tf32.f32 "
        "{%0,%1,%2,%3}, {%4,%5,%6,%7}, {%8,%9}, {%0,%1,%2,%3};"
        : "+f"(c[0]), "+f"(c[1]), "+f"(c[2]), "+f"(c[3])
        : "r"(a[0]), "r"(a[1]), "r"(a[2]), "r"(a[3]), "r"(b[0]), "r"(b[1]));
}

// ---------------- setup ----------------
__global__ void zero_k(int* degi, int* cur, float* sums, float* cnt) {
    int i = blockIdx.x * blockDim.x + threadIdx.x;
    if (i < NN) { degi[i] = 0; cur[i] = 0; }
    if (i < GG * HH) sums[i] = 0.0f;
    if (i < GG) cnt[i] = 0.0f;
}

__global__ void count_k(const int* __restrict__ col, int* degi) {
    int e = blockIdx.x * blockDim.x + threadIdx.x;
    if (e < EE) atomicAdd(&degi[col[e]], 1);
}

__global__ void dinv_cnt_k(const int* __restrict__ degi, float* __restrict__ dinv,
                           const int* __restrict__ batch, float* cnt) {
    int i = blockIdx.x * blockDim.x + threadIdx.x;
    if (i < NN) {
        dinv[i] = rsqrtf((float)(degi[i] + 1));   // +1 self-loop
        atomicAdd(&cnt[batch[i]], 1.0f);
    }
}

// ---------------- multi-block exclusive scan ----------------
__global__ __launch_bounds__(SCAN_T)
void scan1_k(const int* __restrict__ deg, int* __restrict__ off, int* __restrict__ bsum) {
    __shared__ int wsum[32];
    int tid = threadIdx.x, lane = tid & 31, wid = tid >> 5;
    int i = blockIdx.x * SCAN_T + tid;
    int v = (i < NN) ? deg[i] : 0;
    int x = v;
    #pragma unroll
    for (int o = 1; o < 32; o <<= 1) {
        int t = __shfl_up_sync(0xffffffffu, x, o);
        if (lane >= o) x += t;
    }
    if (lane == 31) wsum[wid] = x;
    __syncthreads();
    if (wid == 0) {
        int y = wsum[lane];
        #pragma unroll
        for (int o = 1; o < 32; o <<= 1) {
            int t = __shfl_up_sync(0xffffffffu, y, o);
            if (lane >= o) y += t;
        }
        wsum[lane] = y;
    }
    __syncthreads();
    int incl = x + (wid ? wsum[wid - 1] : 0);
    if (i < NN) off[i + 1] = incl;
    if (tid == SCAN_T - 1) bsum[blockIdx.x] = incl;
}

__global__ void scan2_k(int* __restrict__ bsum) {
    int lane = threadIdx.x & 31;
    int i0 = lane, i1 = lane + 32;
    int v0 = (i0 < SCAN_B) ? bsum[i0] : 0;
    int v1 = (i1 < SCAN_B) ? bsum[i1] : 0;
    int x0 = v0;
    #pragma unroll
    for (int o = 1; o < 32; o <<= 1) {
        int t = __shfl_up_sync(0xffffffffu, x0, o);
        if (lane >= o) x0 += t;
    }
    int tot0 = __shfl_sync(0xffffffffu, x0, 31);
    int x1 = v1;
    #pragma unroll
    for (int o = 1; o < 32; o <<= 1) {
        int t = __shfl_up_sync(0xffffffffu, x1, o);
        if (lane >= o) x1 += t;
    }
    if (i0 < SCAN_B) bsum[i0] = x0 - v0;
    if (i1 < SCAN_B) bsum[i1] = x1 - v1 + tot0;
}

__global__ __launch_bounds__(SCAN_T)
void scan3_k(int* __restrict__ off, const int* __restrict__ bsum) {
    int i = blockIdx.x * SCAN_T + threadIdx.x;
    if (i == 0) off[0] = 0;
    if (i < NN) off[i + 1] += bsum[blockIdx.x];
}

__global__ void scatter_k(const int* __restrict__ row, const int* __restrict__ col,
                          const int* __restrict__ off, int* cur, int* __restrict__ csrc) {
    int e = blockIdx.x * blockDim.x + threadIdx.x;
    if (e >= EE) return;
    int c = col[e];
    int pos = off[c] + atomicAdd(&cur[c], 1);
    csrc[pos] = row[e];
}

// ---------------- 3xTF32 tensor-core GEMM: xw = (relu?)A @ W ----------------
// CTA: 256 threads, 128x128 tile. Warp: 32 rows x 64 cols (2 m-tiles x 8 n-tiles).
// W fully resident in smem; A k-chunked 128x32 cp.async double-buffered.
template <int RELU>
__global__ __launch_bounds__(256, 2)
void gemm_tc_k(const float* __restrict__ A, const float* __restrict__ W,
               float* __restrict__ xw) {
    extern __shared__ float smem[];
    float* Ws = smem;                        // [128][WS_STRIDE]
    float* As = smem + SMEM_W_FLOATS;        // 2 x [128][AS_STRIDE]

    const int tid  = threadIdx.x;
    const int warp = tid >> 5;
    const int lane = tid & 31;
    const int gid  = lane >> 2;              // 0..7
    const int tig  = lane & 3;               // 0..3
    const int mBase = (warp & 3) * 32;
    const int nBase = (warp >> 2) * 64;
    const int rowG  = blockIdx.x * 128;

    // W load: 4096 float4, 16 per thread
    #pragma unroll
    for (int i = 0; i < 16; i++) {
        int id = tid + i * 256;
        int r  = id >> 5;
        int c4 = (id & 31) * 4;
        cp_async16(&Ws[r * WS_STRIDE + c4], &W[r * 128 + c4]);
    }
    // A chunk 0: 1024 float4, 4 per thread
    #pragma unroll
    for (int i = 0; i < 4; i++) {
        int id = tid + i * 256;
        int r  = id >> 3;
        int c4 = (id & 7) * 4;
        int gr = rowG + r; if (gr > NN - 1) gr = NN - 1;
        cp_async16(&As[r * AS_STRIDE + c4], &A[(size_t)gr * HH + c4]);
    }
    cp_commit();

    float c[2][8][4];
    #pragma unroll
    for (int mt = 0; mt < 2; mt++)
        #pragma unroll
        for (int nt = 0; nt < 8; nt++)
            #pragma unroll
            for (int j = 0; j < 4; j++) c[mt][nt][j] = 0.0f;

    #pragma unroll 1
    for (int chunk = 0; chunk < 4; chunk++) {
        int buf = chunk & 1;
        if (chunk < 3) {
            float* Ad = As + (buf ^ 1) * SMEM_A_FLOATS;
            #pragma unroll
            for (int i = 0; i < 4; i++) {
                int id = tid + i * 256;
                int r  = id >> 3;
                int c4 = (id & 7) * 4;
                int gr = rowG + r; if (gr > NN - 1) gr = NN - 1;
                cp_async16(&Ad[r * AS_STRIDE + c4],
                           &A[(size_t)gr * HH + (chunk + 1) * 32 + c4]);
            }
            cp_commit();
            cp_wait<1>();
        } else {
            cp_wait<0>();
        }
        __syncthreads();

        const float* Ab = As + buf * SMEM_A_FLOATS;
        #pragma unroll
        for (int ks = 0; ks < 4; ks++) {
            int k0 = ks * 8;
            unsigned ahi[2][4], alo[2][4];
            #pragma unroll
            for (int mt = 0; mt < 2; mt++) {
                int r0 = mBase + mt * 16;
                float a0 = Ab[(r0 + gid)     * AS_STRIDE + k0 + tig];
                float a1 = Ab[(r0 + gid + 8) * AS_STRIDE + k0 + tig];
                float a2 = Ab[(r0 + gid)     * AS_STRIDE + k0 + tig + 4];
                float a3 = Ab[(r0 + gid + 8) * AS_STRIDE + k0 + tig + 4];
                if (RELU) {
                    a0 = fmaxf(a0, 0.0f); a1 = fmaxf(a1, 0.0f);
                    a2 = fmaxf(a2, 0.0f); a3 = fmaxf(a3, 0.0f);
                }
                ahi[mt][0] = f2tf32(a0); alo[mt][0] = f2tf32(a0 - __uint_as_float(ahi[mt][0]));
                ahi[mt][1] = f2tf32(a1); alo[mt][1] = f2tf32(a1 - __uint_as_float(ahi[mt][1]));
                ahi[mt][2] = f2tf32(a2); alo[mt][2] = f2tf32(a2 - __uint_as_float(ahi[mt][2]));
                ahi[mt][3] = f2tf32(a3); alo[mt][3] = f2tf32(a3 - __uint_as_float(ahi[mt][3]));
            }
            int kb = chunk * 32 + k0;
            #pragma unroll
            for (int nt = 0; nt < 8; nt++) {
                int n0 = nBase + nt * 8;
                float b0f = Ws[(kb + tig)     * WS_STRIDE + n0 + gid];
                float b1f = Ws[(kb + tig + 4) * WS_STRIDE + n0 + gid];
                unsigned bhi[2], blo[2];
                bhi[0] = f2tf32(b0f); blo[0] = f2tf32(b0f - __uint_as_float(bhi[0]));
                bhi[1] = f2tf32(b1f); blo[1] = f2tf32(b1f - __uint_as_float(bhi[1]));
                #pragma unroll
                for (int mt = 0; mt < 2; mt++) {
                    mma_tf32(c[mt][nt], ahi[mt], bhi);   // hi*hi
                    mma_tf32(c[mt][nt], alo[mt], bhi);   // lo*hi
                    mma_tf32(c[mt][nt], ahi[mt], blo);   // hi*lo
                }
            }
        }
        __syncthreads();
    }

    // epilogue
    #pragma unroll
    for (int mt = 0; mt < 2; mt++) {
        #pragma unroll
        for (int nt = 0; nt < 8; nt++) {
            int r0  = rowG + mBase + mt * 16 + gid;
            int col = nBase + nt * 8 + tig * 2;
            if (r0 < NN)
                *reinterpret_cast<float2*>(&xw[(size_t)r0 * HH + col]) =
                    make_float2(c[mt][nt][0], c[mt][nt][1]);
            int r1 = r0 + 8;
            if (r1 < NN)
                *reinterpret_cast<float2*>(&xw[(size_t)r1 * HH + col]) =
                    make_float2(c[mt][nt][2], c[mt][nt][3]);
        }
    }
}

// ---------------- node aggregation (warp per node, register accumulate) ----------------
template <int POOL>
__global__ __launch_bounds__(256)
void agg_node_k(const float* __restrict__ xw, const float* __restrict__ dinv,
                const int* __restrict__ off, const int* __restrict__ csrc,
                const float* __restrict__ bias, float* __restrict__ h,
                const int* __restrict__ batch, float* __restrict__ sums) {
    int n    = (blockIdx.x * blockDim.x + threadIdx.x) >> 5;
    int lane = threadIdx.x & 31;
    if (n >= NN) return;

    float dn = __ldg(&dinv[n]);
    float4 acc = *reinterpret_cast<const float4*>(xw + (size_t)n * HH + lane * 4);
    acc.x *= dn; acc.y *= dn; acc.z *= dn; acc.w *= dn;

    int p = __ldg(&off[n]);
    int e = __ldg(&off[n + 1]);

    for (; p + 1 < e; p += 2) {
        int s0 = __ldg(&csrc[p]);
        int s1 = __ldg(&csrc[p + 1]);
        float w0 = __ldg(&dinv[s0]);
        float w1 = __ldg(&dinv[s1]);
        float4 v0 = *reinterpret_cast<const float4*>(xw + (size_t)s0 * HH + lane * 4);
        float4 v1 = *reinterpret_cast<const float4*>(xw + (size_t)s1 * HH + lane * 4);
        acc.x += v0.x * w0 + v1.x * w1;
        acc.y += v0.y * w0 + v1.y * w1;
        acc.z += v0.z * w0 + v1.z * w1;
        acc.w += v0.w * w0 + v1.w * w1;
    }
    if (p < e) {
        int s0 = __ldg(&csrc[p]);
        float w0 = __ldg(&dinv[s0]);
        float4 v0 = *reinterpret_cast<const float4*>(xw + (size_t)s0 * HH + lane * 4);
        acc.x += v0.x * w0; acc.y += v0.y * w0;
        acc.z += v0.z * w0; acc.w += v0.w * w0;
    }

    float4 b = *reinterpret_cast<const float4*>(bias + lane * 4);
    float4 o;
    o.x = fmaf(acc.x, dn, b.x); o.y = fmaf(acc.y, dn, b.y);
    o.z = fmaf(acc.z, dn, b.z); o.w = fmaf(acc.w, dn, b.w);

    if (POOL) {
        o.x = fmaxf(o.x, 0.0f); o.y = fmaxf(o.y, 0.0f);
        o.z = fmaxf(o.z, 0.0f); o.w = fmaxf(o.w, 0.0f);
        int g = __ldg(&batch[n]);
        float* d = sums + (size_t)g * HH + lane * 4;
        asm volatile("red.global.add.v4.f32 [%0], {%1,%2,%3,%4};"
                     :: "l"(d), "f"(o.x), "f"(o.y), "f"(o.z), "f"(o.w) : "memory");
    } else {
        *reinterpret_cast<float4*>(h + (size_t)n * HH + lane * 4) = o;
    }
}

// ---------------- head: mean -> FC -> log_softmax ----------------
__global__ void head_k(const float* __restrict__ sums, const float* __restrict__ cnt,
                       const float* __restrict__ Wfc, const float* __restrict__ bfc,
                       float* __restrict__ out) {
    int g = blockIdx.x;
    int lane = threadIdx.x;
    float inv = 1.0f / fmaxf(cnt[g], 1.0f);
    float p[4];
    #pragma unroll
    for (int i = 0; i < 4; i++)
        p[i] = sums[(size_t)g * HH + lane * 4 + i] * inv;

    float logits[OUTD];
    #pragma unroll
    for (int o = 0; o < OUTD; o++) {
        float s = 0.0f;
        #pragma unroll
        for (int i = 0; i < 4; i++)
            s = fmaf(p[i], __ldg(&Wfc[(size_t)(lane * 4 + i) * OUTD + o]), s);
        #pragma unroll
        for (int off = 16; off > 0; off >>= 1)
            s += __shfl_xor_sync(0xffffffffu, s, off);
        logits[o] = s + __ldg(&bfc[o]);
    }
    if (lane == 0) {
        float m = logits[0];
        #pragma unroll
        for (int o = 1; o < OUTD; o++) m = fmaxf(m, logits[o]);
        float lse = 0.0f;
        #pragma unroll
        for (int o = 0; o < OUTD; o++) lse += expf(logits[o] - m);
        lse = logf(lse);
        #pragma unroll
        for (int o = 0; o < OUTD; o++)
            out[(size_t)g * OUTD + o] = logits[o] - m - lse;
    }
}

// ---------------- launcher ----------------
extern "C" void kernel_launch(void* const* d_in, const int* in_sizes, int n_in,
                              void* d_out, int out_size) {
    const float* x    = (const float*)d_in[0];
    const int*   ei   = (const int*)d_in[1];
    const int*   batch= (const int*)d_in[2];
    const float* W1   = (const float*)d_in[3];
    const float* b1   = (const float*)d_in[4];
    const float* W2   = (const float*)d_in[5];
    const float* b2   = (const float*)d_in[6];
    const float* Wfc  = (const float*)d_in[7];
    const float* bfc  = (const float*)d_in[8];
    float* out = (float*)d_out;

    const int* row = ei;
    const int* col = ei + EE;

    float* bufA = nullptr; cudaGetSymbolAddress((void**)&bufA, g_bufA);
    float* bufB = nullptr; cudaGetSymbolAddress((void**)&bufB, g_bufB);
    float* dinv = nullptr; cudaGetSymbolAddress((void**)&dinv, g_dinv);
    int*   degi = nullptr; cudaGetSymbolAddress((void**)&degi, g_degi);
    int*   off  = nullptr; cudaGetSymbolAddress((void**)&off,  g_off);
    int*   cur  = nullptr; cudaGetSymbolAddress((void**)&cur,  g_cur);
    int*   csrc = nullptr; cudaGetSymbolAddress((void**)&csrc, g_csrc);
    int*   bsum = nullptr; cudaGetSymbolAddress((void**)&bsum, g_bsum);
    float* sums = nullptr; cudaGetSymbolAddress((void**)&sums, g_sums);
    float* cnt  = nullptr; cudaGetSymbolAddress((void**)&cnt,  g_cnt);

    cudaFuncSetAttribute(gemm_tc_k<0>, cudaFuncAttributeMaxDynamicSharedMemorySize,
                         GEMM_SMEM_BYTES);
    cudaFuncSetAttribute(gemm_tc_k<1>, cudaFuncAttributeMaxDynamicSharedMemorySize,
                         GEMM_SMEM_BYTES);

    const int T = 256;
    const int GB = (NN + 127) / 128;   // 313 gemm CTAs

    // setup: degrees, dinv, graph-size histogram, CSC build
    zero_k<<<(NN + T - 1) / T, T>>>(degi, cur, sums, cnt);
    count_k<<<(EE + T - 1) / T, T>>>(col, degi);
    dinv_cnt_k<<<(NN + T - 1) / T, T>>>(degi, dinv, batch, cnt);
    scan1_k<<<SCAN_B, SCAN_T>>>(degi, off, bsum);
    scan2_k<<<1, 32>>>(bsum);
    scan3_k<<<SCAN_B, SCAN_T>>>(off, bsum);
    scatter_k<<<(EE + T - 1) / T, T>>>(row, col, off, cur, csrc);

    // layer 1
    gemm_tc_k<0><<<GB, 256, GEMM_SMEM_BYTES>>>(x, W1, bufA);
    agg_node_k<0><<<(NN * 32 + T - 1) / T, T>>>(bufA, dinv, off, csrc, b1, bufB, nullptr, nullptr);

    // layer 2 (pool fused into aggregation)
    gemm_tc_k<1><<<GB, 256, GEMM_SMEM_BYTES>>>(bufB, W2, bufA);
    agg_node_k<1><<<(NN * 32 + T - 1) / T, T>>>(bufA, dinv, off, csrc, b2, nullptr, batch, sums);

    // head
    head_k<<<GG, 32>>>(sums, cnt, Wfc, bfc, out);
}